// round 9
// baseline (speedup 1.0000x reference)
#include <cuda_runtime.h>
#include <cuda_fp16.h>
#include <cstdint>

#define N_ENTITY 64368
#define N_REL    12
#define DIM      128
#define NB       8
#define N_ITEM   6924
#define EDGES    1000000
#define BATCH    128
#define SEQL     32

#define SCAN_BLOCKS 63   // 63 * 1024 = 64512 >= N_ENTITY; all blocks co-resident

#define W_CHUNKS (N_ENTITY * 32)   // entity x float4-col chunks

// ---------------- device scratch (static, allocation-free) ----------------
__device__ __align__(128) __half g_w[(size_t)N_REL * N_ENTITY * DIM];  // ~198 MB
__device__ __align__(128) float  g_nodes[(size_t)N_ENTITY * DIM];      // ~33 MB
__device__ __align__(128) float  g_u[BATCH * DIM];
__device__ int g_deg[N_ENTITY];
__device__ int g_off[N_ENTITY + 1];
__device__ int g_cursor[N_ENTITY];
__device__ int g_sorted[EDGES];
__device__ volatile int g_blk_incl[SCAN_BLOCKS];
__device__ volatile int g_blk_flag[SCAN_BLOCKS];

// ---------------- K-W: w[r,n,d] = sum_b att[r,b]*basis[b,n,d] (fp16) ---------
__global__ void k_compute_w(const float* __restrict__ basis,
                            const float* __restrict__ att) {
    __shared__ float att_s[N_REL * NB];
    if (threadIdx.x < N_REL * NB) att_s[threadIdx.x] = att[threadIdx.x];
    __syncthreads();

    int tid = blockIdx.x * blockDim.x + threadIdx.x;
    if (tid >= W_CHUNKS) return;
    int n = tid >> 5;        // entity
    int c = tid & 31;        // float4 chunk within DIM

    float4 bv[NB];
#pragma unroll
    for (int b = 0; b < NB; b++)
        bv[b] = *(const float4*)(basis + ((size_t)b * N_ENTITY + n) * DIM + c * 4);

#pragma unroll
    for (int r = 0; r < N_REL; r++) {
        float4 o = make_float4(0.f, 0.f, 0.f, 0.f);
#pragma unroll
        for (int b = 0; b < NB; b++) {
            float a = att_s[r * NB + b];
            o.x += a * bv[b].x; o.y += a * bv[b].y;
            o.z += a * bv[b].z; o.w += a * bv[b].w;
        }
        __half2 h0 = __floats2half2_rn(o.x, o.y);
        __half2 h1 = __floats2half2_rn(o.z, o.w);
        __half2* p = (__half2*)(g_w + ((size_t)r * N_ENTITY + n) * DIM + c * 4);
        p[0] = h0;
        p[1] = h1;
    }
}

// ---------------- K1: zero degree histogram + lookback flags ----------------
__global__ void k_zero_deg() {
    int i = blockIdx.x * blockDim.x + threadIdx.x;
    if (i < N_ENTITY) g_deg[i] = 0;
    if (i < SCAN_BLOCKS) { g_blk_flag[i] = 0; g_blk_incl[i] = 0; }
}

// ---------------- K2: histogram of dst ----------------
__global__ void k_hist(const int* __restrict__ dst) {
    int e = blockIdx.x * blockDim.x + threadIdx.x;
    if (e < EDGES) atomicAdd(&g_deg[dst[e]], 1);
}

// ---------------- block-wide inclusive scan helper ----------------
__device__ __forceinline__ int block_incl_scan(int v, int t) {
    __shared__ int warp_tot[32];
    int lane = t & 31, wid = t >> 5;
#pragma unroll
    for (int o = 1; o < 32; o <<= 1) {
        int n = __shfl_up_sync(0xffffffffu, v, o);
        if (lane >= o) v += n;
    }
    if (lane == 31) warp_tot[wid] = v;
    __syncthreads();
    if (wid == 0) {
        int w = warp_tot[lane];
#pragma unroll
        for (int o = 1; o < 32; o <<= 1) {
            int n = __shfl_up_sync(0xffffffffu, w, o);
            if (lane >= o) w += n;
        }
        warp_tot[lane] = w;
    }
    __syncthreads();
    if (wid > 0) v += warp_tot[wid - 1];
    return v;
}

// ---------------- K3: single-kernel decoupled-lookback exclusive scan --------
__global__ void k_scan_lookback() {
    int b = blockIdx.x, t = threadIdx.x;
    int idx = b * 1024 + t;
    int v = (idx < N_ENTITY) ? g_deg[idx] : 0;
    int incl = block_incl_scan(v, t);

    __shared__ int s_base;
    if (t == 1023) {
        int block_total = incl;
        if (b == 0) {
            g_blk_incl[0] = block_total;
            __threadfence();
            g_blk_flag[0] = 1;
            s_base = 0;
        } else {
            while (g_blk_flag[b - 1] == 0) { }
            __threadfence();
            int prev = g_blk_incl[b - 1];
            g_blk_incl[b] = prev + block_total;
            __threadfence();
            g_blk_flag[b] = 1;
            s_base = prev;
        }
    }
    __syncthreads();

    int excl = s_base + incl - v;
    if (idx < N_ENTITY) {
        g_off[idx]    = excl;
        g_cursor[idx] = excl;
    }
    if (b == SCAN_BLOCKS - 1 && t == 1023) g_off[N_ENTITY] = EDGES;
}

// ---------------- K4: scatter edges into dst-sorted order ----------------
__global__ void k_scatter(const int* __restrict__ src,
                          const int* __restrict__ dst,
                          const int* __restrict__ type) {
    int e = blockIdx.x * blockDim.x + threadIdx.x;
    if (e < EDGES) {
        int d = dst[e];
        int pos = atomicAdd(&g_cursor[d], 1);
        g_sorted[pos] = src[e] | (type[e] << 20);
    }
}

// ---------------- K5: warp-per-dst aggregation + node update ----------------
__device__ __forceinline__ size_t w_index(int p) {
    int s = p & 0xFFFFF;
    int r = p >> 20;
    return ((size_t)r * N_ENTITY + s) * DIM;
}

__device__ __forceinline__ void acc_raw(float4& acc, uint2 raw) {
    float2 fa = __half22float2(*(__half2*)&raw.x);
    float2 fb = __half22float2(*(__half2*)&raw.y);
    acc.x += fa.x; acc.y += fa.y; acc.z += fb.x; acc.w += fb.y;
}

__global__ void k_aggr(const float* __restrict__ root,
                       const float* __restrict__ bias) {
    int gw   = (blockIdx.x * blockDim.x + threadIdx.x) >> 5;
    int lane = threadIdx.x & 31;
    if (gw >= N_ENTITY) return;

    int start = g_off[gw];
    int end   = g_off[gw + 1];

    float4 acc = make_float4(0.f, 0.f, 0.f, 0.f);
    int e = start;
    // 8-deep MLP: issue 8 independent loads before accumulating
    for (; e + 8 <= end; e += 8) {
        uint2 raw[8];
#pragma unroll
        for (int j = 0; j < 8; j++) {
            int p = g_sorted[e + j];
            raw[j] = *(const uint2*)(g_w + w_index(p) + lane * 4);
        }
#pragma unroll
        for (int j = 0; j < 8; j++) acc_raw(acc, raw[j]);
    }
    for (; e < end; e++) {
        int p = g_sorted[e];
        uint2 raw = *(const uint2*)(g_w + w_index(p) + lane * 4);
        acc_raw(acc, raw);
    }

    int deg = end - start;
    float inv = 1.0f / (float)(deg > 0 ? deg : 1);
    float4 r4 = *(const float4*)(root + (size_t)gw * DIM + lane * 4);
    float4 b4 = *(const float4*)(bias + lane * 4);
    float4 o;
    o.x = acc.x * inv + r4.x + b4.x;
    o.y = acc.y * inv + r4.y + b4.y;
    o.z = acc.z * inv + r4.z + b4.z;
    o.w = acc.w * inv + r4.w + b4.w;
    *(float4*)(g_nodes + (size_t)gw * DIM + lane * 4) = o;
}

// ---------------- K6: attention pooling (one block per batch row) ------------
__global__ void k_pool(const int* __restrict__ seed_ids,
                       const int* __restrict__ seed_len,
                       const float* __restrict__ attn_a,
                       const float* __restrict__ attn_b) {
    __shared__ float h[SEQL][DIM];
    __shared__ float e_sh[SEQL];
    __shared__ float red[4];

    int b = blockIdx.x;
    int d = threadIdx.x;   // 128 threads
    int len = seed_len[b];

    for (int l = 0; l < SEQL; l++) {
        int id = seed_ids[b * SEQL + l];
        h[l][d] = g_nodes[(size_t)id * DIM + d];
    }
    __syncthreads();

    float bd = attn_b[d];
    for (int l = 0; l < SEQL; l++) {
        float t = 0.f;
#pragma unroll 8
        for (int k = 0; k < DIM; k++)
            t += h[l][k] * __ldg(&attn_a[k * DIM + d]);
        float val = tanhf(t) * bd;
#pragma unroll
        for (int o = 16; o > 0; o >>= 1)
            val += __shfl_down_sync(0xffffffff, val, o);
        if ((d & 31) == 0) red[d >> 5] = val;
        __syncthreads();
        if (d == 0) e_sh[l] = red[0] + red[1] + red[2] + red[3];
        __syncthreads();
    }

    float u = 0.f;
    if (len > 0) {
        float m = -1e30f;
        for (int l = 0; l < len; l++) m = fmaxf(m, e_sh[l]);
        float ssum = 0.f;
        for (int l = 0; l < len; l++) ssum += expf(e_sh[l] - m);
        float rinv = 1.f / ssum;
        for (int l = 0; l < len; l++)
            u += expf(e_sh[l] - m) * rinv * h[l][d];
    }
    g_u[b * DIM + d] = u;
}

// ---------------- K7: scores = u @ nodes[:N_ITEM]^T + out_bias ---------------
#define SCORES_SMEM (BATCH * DIM * 4 + 32 * 33 * 16)

__global__ void k_scores(const float* __restrict__ out_bias,
                         float* __restrict__ out) {
    extern __shared__ float smem[];
    float4* u_sh4 = (float4*)smem;                        // [128][32] float4
    float4* n_sh4 = (float4*)(smem + BATCH * DIM);        // [32][33] float4 (padded)

    int t  = threadIdx.x;                                  // 256 threads
    int i0 = blockIdx.x * 32;

    const float4* gu4 = (const float4*)g_u;
    for (int idx = t; idx < BATCH * DIM / 4; idx += 256)
        u_sh4[idx] = gu4[idx];

    const float4* gn4 = (const float4*)g_nodes;
    for (int idx = t; idx < 32 * 32; idx += 256) {
        int r = idx >> 5, c = idx & 31;
        n_sh4[r * 33 + c] = gn4[(size_t)(i0 + r) * 32 + c];
    }
    __syncthreads();

    int tx = t & 31;     // item within tile
    int ty = t >> 5;     // 0..7, b = ty + 8*j

    float acc[16];
#pragma unroll
    for (int j = 0; j < 16; j++) acc[j] = 0.f;

    for (int d4 = 0; d4 < 32; d4++) {
        float4 nv = n_sh4[tx * 33 + d4];
#pragma unroll
        for (int j = 0; j < 16; j++) {
            float4 uv = u_sh4[(ty + 8 * j) * 32 + d4];
            acc[j] += nv.x * uv.x + nv.y * uv.y + nv.z * uv.z + nv.w * uv.w;
        }
    }

    int i = i0 + tx;
    if (i < N_ITEM) {
        float ob = out_bias[i];
#pragma unroll
        for (int j = 0; j < 16; j++)
            out[(size_t)(ty + 8 * j) * N_ITEM + i] = acc[j] + ob;
    }
}

// ---------------- launch: fork-join DAG ----------------
extern "C" void kernel_launch(void* const* d_in, const int* in_sizes, int n_in,
                              void* d_out, int out_size) {
    const int*   edge_idx  = (const int*)d_in[0];
    const int*   edge_type = (const int*)d_in[1];
    const int*   seed_ids  = (const int*)d_in[2];
    const int*   seed_len  = (const int*)d_in[3];
    // d_in[4] = labels (unused for scores)
    const float* basis     = (const float*)d_in[5];
    const float* att       = (const float*)d_in[6];
    const float* root      = (const float*)d_in[7];
    const float* rgcn_bias = (const float*)d_in[8];
    const float* attn_a    = (const float*)d_in[9];
    const float* attn_b    = (const float*)d_in[10];
    const float* out_bias  = (const float*)d_in[11];
    float* out = (float*)d_out;

    const int* src = edge_idx;
    const int* dst = edge_idx + EDGES;

    // One-time side-stream/event setup (first call is the uncaptured
    // correctness run; reused verbatim on the capture call).
    static cudaStream_t s2 = nullptr;
    static cudaEvent_t  ev_fork = nullptr, ev_join = nullptr;
    static bool tried = false, have_stream = false;
    if (!tried) {
        tried = true;
        if (cudaStreamCreateWithFlags(&s2, cudaStreamNonBlocking) == cudaSuccess &&
            cudaEventCreateWithFlags(&ev_fork, cudaEventDisableTiming) == cudaSuccess &&
            cudaEventCreateWithFlags(&ev_join, cudaEventDisableTiming) == cudaSuccess)
            have_stream = true;
        cudaFuncSetAttribute(k_scores, cudaFuncAttributeMaxDynamicSharedMemorySize,
                             SCORES_SMEM);
    }

    if (have_stream) {
        // fork: w-build on side stream, sort chain on main stream
        cudaEventRecord(ev_fork, 0);
        cudaStreamWaitEvent(s2, ev_fork, 0);
        k_compute_w<<<(W_CHUNKS + 255) / 256, 256, 0, s2>>>(basis, att);
        cudaEventRecord(ev_join, s2);

        k_zero_deg<<<(N_ENTITY + 255) / 256, 256>>>();
        k_hist<<<(EDGES + 255) / 256, 256>>>(dst);
        k_scan_lookback<<<SCAN_BLOCKS, 1024>>>();
        k_scatter<<<(EDGES + 255) / 256, 256>>>(src, dst, edge_type);

        cudaStreamWaitEvent(0, ev_join, 0);   // join before aggr
    } else {
        // sequential fallback
        k_compute_w<<<(W_CHUNKS + 255) / 256, 256>>>(basis, att);
        k_zero_deg<<<(N_ENTITY + 255) / 256, 256>>>();
        k_hist<<<(EDGES + 255) / 256, 256>>>(dst);
        k_scan_lookback<<<SCAN_BLOCKS, 1024>>>();
        k_scatter<<<(EDGES + 255) / 256, 256>>>(src, dst, edge_type);
    }

    k_aggr<<<(N_ENTITY * 32 + 255) / 256, 256>>>(root, rgcn_bias);
    k_pool<<<BATCH, DIM>>>(seed_ids, seed_len, attn_a, attn_b);
    k_scores<<<(N_ITEM + 31) / 32, 256, SCORES_SMEM>>>(out_bias, out);
}

// round 10
// speedup vs baseline: 1.2673x; 1.2673x over previous
#include <cuda_runtime.h>
#include <cstdint>

#define N_ENTITY 64368
#define N_REL    12
#define DIM      128
#define NB       8
#define N_ITEM   6924
#define EDGES    1000000
#define BATCH    128
#define SEQL     32

#define SCAN_BLOCKS 63   // 63 * 1024 = 64512 >= N_ENTITY

// ---------------- device scratch (static, allocation-free) ----------------
__device__ __align__(128) float g_aggr[(size_t)N_ENTITY * DIM];   // ~33 MB (L2-resident)
__device__ __align__(128) float g_nodes[(size_t)N_ENTITY * DIM];  // ~33 MB
__device__ __align__(128) float g_u[BATCH * DIM];
__device__ int g_deg_in[N_ENTITY];    // in-degree (mean normalization)
__device__ int g_cnt_src[N_ENTITY];   // out-degree (sort key histogram)
__device__ int g_off[N_ENTITY + 1];
__device__ int g_cursor[N_ENTITY];
__device__ int g_sorted[EDGES];       // dst | type<<20, grouped by src
__device__ int g_part[SCAN_BLOCKS];

// ---------------- K1: zero aggr + histograms ----------------
__global__ void k_init() {
    int i = blockIdx.x * blockDim.x + threadIdx.x;   // one float4 each
    if (i < N_ENTITY * (DIM / 4))
        *(float4*)(g_aggr + (size_t)i * 4) = make_float4(0.f, 0.f, 0.f, 0.f);
    if (i < N_ENTITY) { g_deg_in[i] = 0; g_cnt_src[i] = 0; }
}

// ---------------- K2: histograms (out-deg for sort, in-deg for mean) --------
__global__ void k_hist(const int* __restrict__ src,
                       const int* __restrict__ dst) {
    int e = blockIdx.x * blockDim.x + threadIdx.x;
    if (e < EDGES) {
        atomicAdd(&g_cnt_src[src[e]], 1);
        atomicAdd(&g_deg_in[dst[e]], 1);
    }
}

// ---------------- block-wide inclusive scan helper ----------------
__device__ __forceinline__ int block_incl_scan(int v, int t) {
    __shared__ int warp_tot[32];
    int lane = t & 31, wid = t >> 5;
#pragma unroll
    for (int o = 1; o < 32; o <<= 1) {
        int n = __shfl_up_sync(0xffffffffu, v, o);
        if (lane >= o) v += n;
    }
    if (lane == 31) warp_tot[wid] = v;
    __syncthreads();
    if (wid == 0) {
        int w = warp_tot[lane];
#pragma unroll
        for (int o = 1; o < 32; o <<= 1) {
            int n = __shfl_up_sync(0xffffffffu, w, o);
            if (lane >= o) w += n;
        }
        warp_tot[lane] = w;
    }
    __syncthreads();
    if (wid > 0) v += warp_tot[wid - 1];
    return v;
}

// ---------------- K3a: per-block partial sums of out-degree ----------------
__global__ void k_partial() {
    int idx = blockIdx.x * 1024 + threadIdx.x;
    int v = (idx < N_ENTITY) ? g_cnt_src[idx] : 0;
    int incl = block_incl_scan(v, threadIdx.x);
    if (threadIdx.x == 1023) g_part[blockIdx.x] = incl;
}

// ---------------- K3b: offsets (each block re-scans the 63 partials) --------
__global__ void k_offsets() {
    int b = blockIdx.x, t = threadIdx.x;
    int idx = b * 1024 + t;
    int v = (idx < N_ENTITY) ? g_cnt_src[idx] : 0;
    int incl = block_incl_scan(v, t);
    __syncthreads();

    int pv = (t < SCAN_BLOCKS) ? g_part[t] : 0;
    int pincl = block_incl_scan(pv, t);

    __shared__ int base_s;
    if (b == 0) { if (t == 0) base_s = 0; }
    else if (t == b - 1) base_s = pincl;
    __syncthreads();

    int excl = base_s + incl - v;
    if (idx < N_ENTITY) {
        g_off[idx]    = excl;
        g_cursor[idx] = excl;
    }
    if (b == SCAN_BLOCKS - 1 && t == 1023) g_off[N_ENTITY] = EDGES;
}

// ---------------- K4: scatter edges grouped by src ----------------
__global__ void k_scatter(const int* __restrict__ src,
                          const int* __restrict__ dst,
                          const int* __restrict__ type) {
    int e = blockIdx.x * blockDim.x + threadIdx.x;
    if (e < EDGES) {
        int s = src[e];
        int pos = atomicAdd(&g_cursor[s], 1);
        g_sorted[pos] = dst[e] | (type[e] << 20);
    }
}

// ---------------- K5: warp-per-src message + L2 scatter-add ----------------
// msg[d] = sum_b att[type,b] * basis[b,src,d]; red.v4 into g_aggr[dst]
__global__ void k_msg(const float* __restrict__ basis,
                      const float* __restrict__ att) {
    __shared__ float att_s[N_REL * NB];
    if (threadIdx.x < N_REL * NB) att_s[threadIdx.x] = att[threadIdx.x];
    __syncthreads();

    int gw   = (blockIdx.x * blockDim.x + threadIdx.x) >> 5;
    int lane = threadIdx.x & 31;
    if (gw >= N_ENTITY) return;

    int start = g_off[gw];
    int end   = g_off[gw + 1];
    if (start == end) return;

    float4 bv[NB];
#pragma unroll
    for (int b = 0; b < NB; b++)
        bv[b] = *(const float4*)(basis + ((size_t)b * N_ENTITY + gw) * DIM + lane * 4);

    for (int e = start; e < end; e++) {
        int p = g_sorted[e];
        int dst = p & 0xFFFFF;
        const float* a = att_s + (p >> 20) * NB;
        float4 m = make_float4(0.f, 0.f, 0.f, 0.f);
#pragma unroll
        for (int b = 0; b < NB; b++) {
            float c = a[b];
            m.x += c * bv[b].x; m.y += c * bv[b].y;
            m.z += c * bv[b].z; m.w += c * bv[b].w;
        }
        float* q = g_aggr + (size_t)dst * DIM + lane * 4;
        asm volatile("red.global.add.v4.f32 [%0], {%1, %2, %3, %4};"
                     :: "l"(q), "f"(m.x), "f"(m.y), "f"(m.z), "f"(m.w)
                     : "memory");
    }
}

// ---------------- K6: nodes = aggr/max(deg,1) + root + bias ----------------
__global__ void k_final(const float* __restrict__ root,
                        const float* __restrict__ bias) {
    int tid = blockIdx.x * blockDim.x + threadIdx.x;
    if (tid >= N_ENTITY * (DIM / 4)) return;
    int n = tid >> 5;
    int c = tid & 31;

    int deg = g_deg_in[n];
    float inv = 1.0f / (float)(deg > 0 ? deg : 1);
    float4 a  = *(const float4*)(g_aggr + (size_t)n * DIM + c * 4);
    float4 r4 = *(const float4*)(root + (size_t)n * DIM + c * 4);
    float4 b4 = *(const float4*)(bias + c * 4);
    float4 o;
    o.x = a.x * inv + r4.x + b4.x;
    o.y = a.y * inv + r4.y + b4.y;
    o.z = a.z * inv + r4.z + b4.z;
    o.w = a.w * inv + r4.w + b4.w;
    *(float4*)(g_nodes + (size_t)n * DIM + c * 4) = o;
}

// ---------------- K7: attention pooling (one block per batch row) ------------
__global__ void k_pool(const int* __restrict__ seed_ids,
                       const int* __restrict__ seed_len,
                       const float* __restrict__ attn_a,
                       const float* __restrict__ attn_b) {
    __shared__ float h[SEQL][DIM];
    __shared__ float e_sh[SEQL];
    __shared__ float red[4];

    int b = blockIdx.x;
    int d = threadIdx.x;   // 128 threads
    int len = seed_len[b];

    for (int l = 0; l < SEQL; l++) {
        int id = seed_ids[b * SEQL + l];
        h[l][d] = g_nodes[(size_t)id * DIM + d];
    }
    __syncthreads();

    float bd = attn_b[d];
    for (int l = 0; l < SEQL; l++) {
        float t = 0.f;
#pragma unroll 8
        for (int k = 0; k < DIM; k++)
            t += h[l][k] * __ldg(&attn_a[k * DIM + d]);
        float val = tanhf(t) * bd;
#pragma unroll
        for (int o = 16; o > 0; o >>= 1)
            val += __shfl_down_sync(0xffffffff, val, o);
        if ((d & 31) == 0) red[d >> 5] = val;
        __syncthreads();
        if (d == 0) e_sh[l] = red[0] + red[1] + red[2] + red[3];
        __syncthreads();
    }

    float u = 0.f;
    if (len > 0) {
        float m = -1e30f;
        for (int l = 0; l < len; l++) m = fmaxf(m, e_sh[l]);
        float ssum = 0.f;
        for (int l = 0; l < len; l++) ssum += expf(e_sh[l] - m);
        float rinv = 1.f / ssum;
        for (int l = 0; l < len; l++)
            u += expf(e_sh[l] - m) * rinv * h[l][d];
    }
    g_u[b * DIM + d] = u;
}

// ---------------- K8: scores = u @ nodes[:N_ITEM]^T + out_bias ---------------
#define SCORES_SMEM (BATCH * DIM * 4 + 32 * 33 * 16)

__global__ void k_scores(const float* __restrict__ out_bias,
                         float* __restrict__ out) {
    extern __shared__ float smem[];
    float4* u_sh4 = (float4*)smem;                        // [128][32] float4
    float4* n_sh4 = (float4*)(smem + BATCH * DIM);        // [32][33] float4 (padded)

    int t  = threadIdx.x;                                  // 256 threads
    int i0 = blockIdx.x * 32;

    const float4* gu4 = (const float4*)g_u;
    for (int idx = t; idx < BATCH * DIM / 4; idx += 256)
        u_sh4[idx] = gu4[idx];

    const float4* gn4 = (const float4*)g_nodes;
    for (int idx = t; idx < 32 * 32; idx += 256) {
        int r = idx >> 5, c = idx & 31;
        n_sh4[r * 33 + c] = gn4[(size_t)(i0 + r) * 32 + c];
    }
    __syncthreads();

    int tx = t & 31;     // item within tile
    int ty = t >> 5;     // 0..7, b = ty + 8*j

    float acc[16];
#pragma unroll
    for (int j = 0; j < 16; j++) acc[j] = 0.f;

    for (int d4 = 0; d4 < 32; d4++) {
        float4 nv = n_sh4[tx * 33 + d4];
#pragma unroll
        for (int j = 0; j < 16; j++) {
            float4 uv = u_sh4[(ty + 8 * j) * 32 + d4];
            acc[j] += nv.x * uv.x + nv.y * uv.y + nv.z * uv.z + nv.w * uv.w;
        }
    }

    int i = i0 + tx;
    if (i < N_ITEM) {
        float ob = out_bias[i];
#pragma unroll
        for (int j = 0; j < 16; j++)
            out[(size_t)(ty + 8 * j) * N_ITEM + i] = acc[j] + ob;
    }
}

// ---------------- launch (single stream) ----------------
extern "C" void kernel_launch(void* const* d_in, const int* in_sizes, int n_in,
                              void* d_out, int out_size) {
    const int*   edge_idx  = (const int*)d_in[0];
    const int*   edge_type = (const int*)d_in[1];
    const int*   seed_ids  = (const int*)d_in[2];
    const int*   seed_len  = (const int*)d_in[3];
    // d_in[4] = labels (unused for scores)
    const float* basis     = (const float*)d_in[5];
    const float* att       = (const float*)d_in[6];
    const float* root      = (const float*)d_in[7];
    const float* rgcn_bias = (const float*)d_in[8];
    const float* attn_a    = (const float*)d_in[9];
    const float* attn_b    = (const float*)d_in[10];
    const float* out_bias  = (const float*)d_in[11];
    float* out = (float*)d_out;

    const int* src = edge_idx;
    const int* dst = edge_idx + EDGES;

    cudaFuncSetAttribute(k_scores, cudaFuncAttributeMaxDynamicSharedMemorySize,
                         SCORES_SMEM);

    k_init<<<(N_ENTITY * 32 + 255) / 256, 256>>>();
    k_hist<<<(EDGES + 255) / 256, 256>>>(src, dst);
    k_partial<<<SCAN_BLOCKS, 1024>>>();
    k_offsets<<<SCAN_BLOCKS, 1024>>>();
    k_scatter<<<(EDGES + 255) / 256, 256>>>(src, dst, edge_type);
    k_msg<<<(N_ENTITY * 32 + 255) / 256, 256>>>(basis, att);
    k_final<<<(N_ENTITY * 32 + 255) / 256, 256>>>(root, rgcn_bias);
    k_pool<<<BATCH, DIM>>>(seed_ids, seed_len, attn_a, attn_b);
    k_scores<<<(N_ITEM + 31) / 32, 256, SCORES_SMEM>>>(out_bias, out);
}